// round 12
// baseline (speedup 1.0000x reference)
#include <cuda_runtime.h>
#include <math.h>

#define BB 512
#define PP 256
#define TT 128
#define VV 10000
#define EE 300
#define HH 256
#define NCC 64
#define NOO 256
#define BN_EPS 1e-5f
#define NITEMS ((TT-1)*BB)          // 65024
#define HEAD_ITEMS 32               // items per head block (shared W)
#define ITEM_CAP (NITEMS + NCC*HEAD_ITEMS)  // 67072
#define NBLK 128                    // persistent grid size (<=148 SMs -> co-resident)

#define WSTRIDE 258                 // [u][k] weight row stride: 8B-aligned, conflict-free 64b LDS
#define WGSZ (32 * WSTRIDE)         // 8256 floats per gate slice
#define ASTRIDE 260                 // activation tile row stride: 16B-aligned float4 stores

typedef unsigned long long u64t;
#define UNPACK2(lo, hi, s) asm("mov.b64 {%0, %1}, %2;" : "=f"(lo), "=f"(hi) : "l"(s))
#define PACK2(d, lo, hi) asm("mov.b64 %0, {%1, %2};" : "=l"(d) : "f"(lo), "f"(hi))
#define FFMA2(d, a, b) asm("fma.rn.f32x2 %0, %1, %2, %0;" : "+l"(d) : "l"(a), "l"(b))

// ---------------- device scratch (no cudaMalloc allowed) ----------------
__device__ float g_encT[VV * 4 * HH];        // token -> lstm gate_x (+b_ih+b_hh)
__device__ float g_chT[NCC * NOO * 3 * HH];  // (prev,val) -> gru gx part
__device__ float g_idxT[NCC * 3 * HH];       // prev -> gru gx part
__device__ float g_progW[BB * 3 * HH];       // per-sample gx part (+b_ih)
__device__ float g_hA[BB * HH];
__device__ float g_hB[BB * HH];
__device__ float g_hall[(TT - 1) * BB * HH]; // all decoder hidden states
__device__ float g_psums[TT * 16 * HH * 2];  // BN partials [t][rowblk][feat][{s,s2}]
__device__ int   g_counts[NCC], g_offs[NCC], g_curs[NCC];
__device__ int   g_items[ITEM_CAP];
__device__ unsigned int g_bar_lstm[16];      // per-row-group barriers (8 blocks each)
__device__ unsigned int g_bar_gru;

__device__ __forceinline__ float sigm(float x) { return 1.f / (1.f + expf(-x)); }

// monotonic-counter barrier over `nb` participating blocks; graph-replay safe
__device__ __forceinline__ void sw_barrier(unsigned int* cnt, unsigned int nb) {
    __threadfence();
    __syncthreads();
    if (threadIdx.x == 0) {
        unsigned int a = atomicAdd(cnt, 1u) + 1u;
        unsigned int target = ((a + nb - 1u) / nb) * nb;
        while (*((volatile unsigned int*)cnt) < target) { __nanosleep(20); }
    }
    __syncthreads();
}

// L2-only (L1-bypass) loads: cross-block data inside persistent kernels
// MUST NOT hit the per-SM non-coherent L1.
__device__ __forceinline__ float4 ldcg4(const float* p) {
    return __ldcg(reinterpret_cast<const float4*>(p));
}
__device__ __forceinline__ float2 ldcg2(const float* p) {
    return __ldcg(reinterpret_cast<const float2*>(p));
}

// ---------------- init: zero output, reset binning scratch ----------------
__global__ __launch_bounds__(256) void init_kernel(float* __restrict__ out, int outN) {
    int stride = gridDim.x * blockDim.x;
    for (int idx = blockIdx.x * blockDim.x + threadIdx.x; idx < outN; idx += stride) {
        out[idx] = 0.f;
        if (idx < ITEM_CAP) g_items[idx] = -1;
        if (idx < NCC) { g_counts[idx] = 0; g_curs[idx] = 0; }
    }
}

// BN stats for decoder step 0 (from h_dec0), deterministic per-rowblock partials
__global__ __launch_bounds__(256) void stats0_kernel(const float* __restrict__ hdec0) {
    int by = blockIdx.x;
    int f = threadIdx.x;
    float s = 0.f, s2 = 0.f;
    for (int r = 0; r < 32; r++) {
        float v = hdec0[(by * 32 + r) * HH + f];
        s += v; s2 += v * v;
    }
    g_psums[((0 * 16 + by) * HH + f) * 2 + 0] = s;
    g_psums[((0 * 16 + by) * HH + f) * 2 + 1] = s2;
}

// ---------------- C = A(MxK) * B(NxK)^T + bias0 + bias1 (dst via selector) ----------------
// f32x2: pack row-pairs (contiguous in As[kk][row]); B scalar broadcast via PACK2
__global__ __launch_bounds__(256) void gemm_nt(const float* __restrict__ Aext, int lda,
                                               const float* __restrict__ Bm, int ldb,
                                               const float* __restrict__ bias0,
                                               const float* __restrict__ bias1,
                                               int M, int N, int K, int dst_id, int src_hB) {
    const float* A = src_hB ? g_hB : Aext;
    float* C = (dst_id == 0) ? g_encT : (dst_id == 1) ? g_chT : (dst_id == 2) ? g_idxT : g_progW;
    __shared__ float As[16][68];
    __shared__ float Bs[16][68];
    int tid = threadIdx.x;
    int tx = tid & 15, ty = tid >> 4;
    int m0 = blockIdx.y * 64, n0 = blockIdx.x * 64;
    u64t acc2[2][4];   // [row-pair][col j], lanes = (m, m+1)
#pragma unroll
    for (int i = 0; i < 2; i++)
#pragma unroll
        for (int j = 0; j < 4; j++) acc2[i][j] = 0ull;

    for (int k0 = 0; k0 < K; k0 += 16) {
#pragma unroll
        for (int p = 0; p < 4; p++) {
            int l = tid + p * 256;
            int row = l >> 4, kk = l & 15;
            int k = k0 + kk;
            int m = m0 + row;
            As[kk][row] = (m < M && k < K) ? A[m * lda + k] : 0.f;
            int n = n0 + row;
            Bs[kk][row] = (n < N && k < K) ? Bm[n * ldb + k] : 0.f;
        }
        __syncthreads();
#pragma unroll
        for (int kk = 0; kk < 16; kk++) {
            u64t a01 = *(const u64t*)&As[kk][ty * 4];
            u64t a23 = *(const u64t*)&As[kk][ty * 4 + 2];
            float4 b4 = *(const float4*)&Bs[kk][tx * 4];
            const float* bp = (const float*)&b4;
#pragma unroll
            for (int j = 0; j < 4; j++) {
                u64t b2;
                PACK2(b2, bp[j], bp[j]);
                FFMA2(acc2[0][j], a01, b2);
                FFMA2(acc2[1][j], a23, b2);
            }
        }
        __syncthreads();
    }
#pragma unroll
    for (int ip = 0; ip < 2; ip++) {
#pragma unroll
        for (int j = 0; j < 4; j++) {
            float vlo, vhi;
            UNPACK2(vlo, vhi, acc2[ip][j]);
            int n = n0 + tx * 4 + j;
            if (n >= N) continue;
            float badd = (bias0 ? bias0[n] : 0.f) + (bias1 ? bias1[n] : 0.f);
            int mA = m0 + ty * 4 + ip * 2;
            if (mA < M) C[mA * N + n] = vlo + badd;
            if (mA + 1 < M) C[(mA + 1) * N + n] = vhi + badd;
        }
    }
}

// ---------------- persistent LSTM: whole-tile smem activation, single sync per step ----------------
// grid 128 = (8 u-tiles) x (16 row-groups); block 256 = 32 (tx=u) x 8 (ty), 4 rows/thread.
// CRITICAL: h ping-pong is re-read every 2 steps -> all hin reads use .cg (L1 bypass);
// per-SM L1 is NOT coherent with other SMs' __stcg writes inside one launch.
__global__ __launch_bounds__(256, 1) void lstm_persist(const float* __restrict__ Whh,
                                                       const int* __restrict__ program,
                                                       const int* __restrict__ plen,
                                                       const float* __restrict__ h0,
                                                       const float* __restrict__ c0) {
    extern __shared__ float sm[];
    float* Wsh = sm;                    // [4][32][WSTRIDE] = 33024 floats
    float* At = sm + 4 * WGSZ;          // [32][ASTRIDE] = 8320 floats (full step tile)

    int tid = threadIdx.x;
    int tx = tid & 31;                  // unit within 32-wide tile
    int ty = tid >> 5;                  // 0..7
    int u0 = (blockIdx.x & 7) * 32;
    int ry = blockIdx.x >> 3;           // row group 0..15
    int r0 = ry * 32;
    int u = u0 + tx;

    // resident Whh slice: Wsh[g][uu][k] (k contiguous -> coalesced load, k-pair LDS.64 reads)
    for (int idx = tid; idx < 4 * 32 * 256; idx += 256) {
        int k = idx & 255;
        int uu = (idx >> 8) & 31;
        int g = idx >> 13;
        Wsh[g * WGSZ + uu * WSTRIDE + k] = Whh[(g * HH + u0 + uu) * HH + k];
    }

    // register-resident state for this thread's 4 cells
    float h_reg[4], c_reg[4];
    int pl[4];
#pragma unroll
    for (int r = 0; r < 4; r++) {
        int R = r0 + ty * 4 + r;
        h_reg[r] = h0[R * HH + u];
        c_reg[r] = c0[R * HH + u];
        pl[r] = plen[R];
    }
    __syncthreads();

    const float* wrow = Wsh + tx * WSTRIDE;

    for (int t = 0; t < PP; t++) {
        const float* hin = (t == 0) ? h0 : ((t & 1) ? g_hA : g_hB);
        float* hout = (t & 1) ? g_hB : g_hA;

        // prefetch gate_x gathers first (DRAM/L2 latency hides under tile load + GEMM)
        float gx0[4], gx1[4], gx2[4], gx3[4];
#pragma unroll
        for (int r = 0; r < 4; r++) {
            int R = r0 + ty * 4 + r;
            int tok = program[R * PP + t];
            const float* gp = g_encT + (size_t)tok * (4 * HH) + u;
            gx0[r] = __ldg(gp);
            gx1[r] = __ldg(gp + HH);
            gx2[r] = __ldg(gp + 2 * HH);
            gx3[r] = __ldg(gp + 3 * HH);
        }

        // whole 32x256 activation tile -> smem (float4 .cg, coalesced), ONE sync
#pragma unroll
        for (int p = 0; p < 8; p++) {
            int l = tid + p * 256;
            int row = l >> 6, c4 = (l & 63) << 2;
            float4 v = ldcg4(&hin[(r0 + row) * HH + c4]);
            *(float4*)&At[row * ASTRIDE + c4] = v;
        }
        __syncthreads();

        u64t acc2[4][4];   // [gate][row], lanes = k-pair partial sums
#pragma unroll
        for (int g = 0; g < 4; g++)
#pragma unroll
            for (int r = 0; r < 4; r++) acc2[g][r] = 0ull;

#pragma unroll 4
        for (int kk = 0; kk < HH; kk += 4) {
            u64t ap[4][2];
#pragma unroll
            for (int r = 0; r < 4; r++) {
                ap[r][0] = *(const u64t*)&At[(ty * 4 + r) * ASTRIDE + kk];
                ap[r][1] = *(const u64t*)&At[(ty * 4 + r) * ASTRIDE + kk + 2];
            }
#pragma unroll
            for (int p = 0; p < 2; p++) {
#pragma unroll
                for (int g = 0; g < 4; g++) {
                    u64t w2 = *(const u64t*)(wrow + g * WGSZ + kk + 2 * p);
                    FFMA2(acc2[g][0], ap[0][p], w2);
                    FFMA2(acc2[g][1], ap[1][p], w2);
                    FFMA2(acc2[g][2], ap[2][p], w2);
                    FFMA2(acc2[g][3], ap[3][p], w2);
                }
            }
        }

#pragma unroll
        for (int r = 0; r < 4; r++) {
            float lo, hi;
            UNPACK2(lo, hi, acc2[0][r]); float vi = lo + hi;
            UNPACK2(lo, hi, acc2[1][r]); float vf = lo + hi;
            UNPACK2(lo, hi, acc2[2][r]); float vg = lo + hi;
            UNPACK2(lo, hi, acc2[3][r]); float vo = lo + hi;
            int R = r0 + ty * 4 + r;
            float ig = sigm(vi + gx0[r]);
            float fg = sigm(vf + gx1[r]);
            float gg = tanhf(vg + gx2[r]);
            float og = sigm(vo + gx3[r]);
            float cnew = fg * c_reg[r] + ig * gg;
            float hnew = og * tanhf(cnew);
            bool valid = t < pl[r];
            float cv = valid ? cnew : c_reg[r];
            float hv = valid ? hnew : h_reg[r];
            c_reg[r] = cv;
            h_reg[r] = hv;
            __stcg(&hout[R * HH + u], hv);
        }
        sw_barrier(&g_bar_lstm[ry], 8u);   // only the 8 blocks of this row group
    }
}

// ---------------- persistent GRU: BN fused into tile load, single sync per step ----------------
__global__ __launch_bounds__(256, 1) void gru_persist(const float* __restrict__ Whh,
                                                      const float* __restrict__ bhh,
                                                      const float* __restrict__ gamma,
                                                      const float* __restrict__ beta,
                                                      const int* __restrict__ trace,
                                                      const int* __restrict__ choices,
                                                      const float* __restrict__ hdec0) {
    extern __shared__ float sm[];
    float* Wsh = sm;                        // [3][32][WSTRIDE] = 24768
    float* At = sm + 3 * WGSZ;              // [32][ASTRIDE] = 8320 (also BN reduce buffer)
    float* s_sc = At + 32 * ASTRIDE;        // [256]
    float* s_sh = s_sc + HH;                // [256]

    int tid = threadIdx.x;
    int tx = tid & 31;
    int ty = tid >> 5;
    int u0 = (blockIdx.x & 7) * 32;
    int ry = blockIdx.x >> 3;
    int r0 = ry * 32;
    int u = u0 + tx;

    for (int idx = tid; idx < 3 * 32 * 256; idx += 256) {
        int k = idx & 255;
        int uu = (idx >> 8) & 31;
        int g = idx >> 13;
        Wsh[g * WGSZ + uu * WSTRIDE + k] = Whh[(g * HH + u0 + uu) * HH + k];
    }

    float bh0 = bhh[u], bh1 = bhh[HH + u], bh2 = bhh[2 * HH + u];
    float gmv = gamma[tid], btv = beta[tid];

    float h_reg[4];
#pragma unroll
    for (int r = 0; r < 4; r++) h_reg[r] = hdec0[(r0 + ty * 4 + r) * HH + u];
    __syncthreads();

    const float* wrow = Wsh + tx * WSTRIDE;

    for (int t = 0; t < TT - 1; t++) {
        const float* hin = (t == 0) ? hdec0 : (g_hall + (size_t)(t - 1) * BB * HH);
        float* hout = g_hall + (size_t)t * BB * HH;

        // prefetch routed-table gathers for epilogue
        float pw0[4], pw1[4], pw2[4], iw0[4], iw1[4], iw2[4], cw0[4], cw1[4], cw2[4];
#pragma unroll
        for (int r = 0; r < 4; r++) {
            int R = r0 + ty * 4 + r;
            int prev = trace[R * TT + t];
            int val = choices[R * NCC + prev];
            const float* pw = g_progW + (size_t)R * (3 * HH) + u;
            const float* iw = g_idxT + (size_t)prev * (3 * HH) + u;
            const float* cw = g_chT + (size_t)(prev * NOO + val) * (3 * HH) + u;
            pw0[r] = __ldg(pw); pw1[r] = __ldg(pw + HH); pw2[r] = __ldg(pw + 2 * HH);
            iw0[r] = __ldg(iw); iw1[r] = __ldg(iw + HH); iw2[r] = __ldg(iw + 2 * HH);
            cw0[r] = __ldg(cw); cw1[r] = __ldg(cw + HH); cw2[r] = __ldg(cw + 2 * HH);
        }

        // BN scale/shift from step-t partial sums (feature = tid, 64b paired loads)
        {
            float s = 0.f, s2 = 0.f;
#pragma unroll
            for (int p = 0; p < 16; p++) {
                float2 pv = ldcg2(&g_psums[((t * 16 + p) * HH + tid) * 2]);
                s += pv.x; s2 += pv.y;
            }
            float mean = s * (1.f / (float)BB);
            float var = fmaxf(s2 * (1.f / (float)BB) - mean * mean, 0.f);
            float inv = rsqrtf(var + BN_EPS);
            float scv = gmv * inv;
            s_sc[tid] = scv;
            s_sh[tid] = btv - mean * scv;
        }
        __syncthreads();   // s_sc/s_sh ready for tile-load normalization

        // whole 32x256 tile, BN applied inline (L1-bypass loads), ONE more sync
#pragma unroll
        for (int p = 0; p < 8; p++) {
            int l = tid + p * 256;
            int row = l >> 6, c4 = (l & 63) << 2;
            float4 v = ldcg4(&hin[(r0 + row) * HH + c4]);
            v.x = v.x * s_sc[c4 + 0] + s_sh[c4 + 0];
            v.y = v.y * s_sc[c4 + 1] + s_sh[c4 + 1];
            v.z = v.z * s_sc[c4 + 2] + s_sh[c4 + 2];
            v.w = v.w * s_sc[c4 + 3] + s_sh[c4 + 3];
            *(float4*)&At[row * ASTRIDE + c4] = v;
        }
        __syncthreads();

        u64t acc2[3][4];
#pragma unroll
        for (int g = 0; g < 3; g++)
#pragma unroll
            for (int r = 0; r < 4; r++) acc2[g][r] = 0ull;

#pragma unroll 4
        for (int kk = 0; kk < HH; kk += 4) {
            u64t ap[4][2];
#pragma unroll
            for (int r = 0; r < 4; r++) {
                ap[r][0] = *(const u64t*)&At[(ty * 4 + r) * ASTRIDE + kk];
                ap[r][1] = *(const u64t*)&At[(ty * 4 + r) * ASTRIDE + kk + 2];
            }
#pragma unroll
            for (int p = 0; p < 2; p++) {
#pragma unroll
                for (int g = 0; g < 3; g++) {
                    u64t w2 = *(const u64t*)(wrow + g * WGSZ + kk + 2 * p);
                    FFMA2(acc2[g][0], ap[0][p], w2);
                    FFMA2(acc2[g][1], ap[1][p], w2);
                    FFMA2(acc2[g][2], ap[2][p], w2);
                    FFMA2(acc2[g][3], ap[3][p], w2);
                }
            }
        }

        float scu = s_sc[u], shu = s_sh[u];
        float ps = 0.f, ps2 = 0.f;
#pragma unroll
        for (int r = 0; r < 4; r++) {
            float lo, hi;
            UNPACK2(lo, hi, acc2[0][r]); float vr = lo + hi;
            UNPACK2(lo, hi, acc2[1][r]); float vz = lo + hi;
            UNPACK2(lo, hi, acc2[2][r]); float vn = lo + hi;
            int R = r0 + ty * 4 + r;
            float gh0 = vr + bh0;
            float gh1 = vz + bh1;
            float gh2 = vn + bh2;
            float gxr = pw0[r] + iw0[r] + cw0[r];
            float gxz = pw1[r] + iw1[r] + cw1[r];
            float gxn = pw2[r] + iw2[r] + cw2[r];
            float rr = sigm(gxr + gh0);
            float zz = sigm(gxz + gh1);
            float nn = tanhf(gxn + rr * gh2);
            float hnb = h_reg[r] * scu + shu;
            float hnew = (1.f - zz) * nn + zz * hnb;
            h_reg[r] = hnew;
            __stcg(&hout[R * HH + u], hnew);
            ps += hnew;
            ps2 += hnew * hnew;
        }

        // deterministic BN partials for step t+1 (reuse At; 64b paired store)
        __syncthreads();
        At[ty * 33 + tx] = ps;
        At[(8 + ty) * 33 + tx] = ps2;
        __syncthreads();
        if (ty == 0) {
            float s = 0.f, s2 = 0.f;
#pragma unroll
            for (int j = 0; j < 8; j++) { s += At[j * 33 + tx]; s2 += At[(8 + j) * 33 + tx]; }
            float2 pv = make_float2(s, s2);
            __stcg(reinterpret_cast<float2*>(&g_psums[(((t + 1) * 16 + ry) * HH + u) * 2]), pv);
        }
        sw_barrier(&g_bar_gru, NBLK);   // BN couples all rows -> full-grid barrier
    }
}

// ---------------- head binning (coalesced: i = b*127 + t, lanes walk t) ----------------
__global__ __launch_bounds__(256) void count_kernel(const int* __restrict__ trace) {
    int i = blockIdx.x * 256 + threadIdx.x;
    if (i >= NITEMS) return;
    int b = i / (TT - 1), t = i - b * (TT - 1);
    int c = trace[b * TT + t + 1];
    if (c != 0) atomicAdd(&g_counts[c], 1);
}

__global__ void prefix_kernel() {
    if (threadIdx.x == 0) {
        int off = 0;
        for (int c = 0; c < NCC; c++) {
            g_offs[c] = off;
            off += ((g_counts[c] + HEAD_ITEMS - 1) / HEAD_ITEMS) * HEAD_ITEMS;
        }
    }
}

__global__ __launch_bounds__(256) void scatter_kernel(const int* __restrict__ trace) {
    int i = blockIdx.x * 256 + threadIdx.x;
    if (i >= NITEMS) return;
    int b = i / (TT - 1), t = i - b * (TT - 1);
    int c = trace[b * TT + t + 1];
    if (c != 0) {
        int pos = g_offs[c] + atomicAdd(&g_curs[c], 1);
        g_items[pos] = (t << 16) | b;
    }
}

// ---------------- routed head: 32 items per block share one 256x256 W (k-pair f32x2) ----------------
__global__ __launch_bounds__(256) void head_kernel(const int* __restrict__ trace,
                                                   const float* __restrict__ infW,
                                                   const float* __restrict__ infB,
                                                   float* __restrict__ out) {
    __shared__ int sIt[HEAD_ITEMS];
    __shared__ float Hs[HEAD_ITEMS][32];
    __shared__ float Ws[256 * 34];   // [o][k] stride 34 -> conflict-free 64b LDS (16-lane phases)
    int tid = threadIdx.x;
    if (tid < HEAD_ITEMS) sIt[tid] = g_items[blockIdx.x * HEAD_ITEMS + tid];
    __syncthreads();
    int it0 = sIt[0];
    if (it0 < 0) return;   // fully-padding block (bins are HEAD_ITEMS-aligned)
    int t0 = it0 >> 16, b0 = it0 & 0xFFFF;
    int c = trace[b0 * TT + t0 + 1];
    const float* W = infW + (size_t)c * NOO * HH;

    u64t acc2[HEAD_ITEMS];
#pragma unroll
    for (int i = 0; i < HEAD_ITEMS; i++) acc2[i] = 0ull;
    int o = tid;
    const float* wrow = Ws + o * 34;

    for (int k0 = 0; k0 < HH; k0 += 32) {
        for (int l = tid; l < HEAD_ITEMS * 32; l += 256) {
            int i = l >> 5, kk = l & 31;
            int it = sIt[i];
            float v = 0.f;
            if (it >= 0) {
                int tt = it >> 16, bb = it & 0xFFFF;
                v = g_hall[((size_t)tt * BB + bb) * HH + k0 + kk];
            }
            Hs[i][kk] = v;
        }
#pragma unroll 8
        for (int l = tid; l < 8192; l += 256) {
            int oo = l >> 5, kk = l & 31;
            Ws[oo * 34 + kk] = W[oo * HH + k0 + kk];
        }
        __syncthreads();
#pragma unroll
        for (int kk = 0; kk < 32; kk += 2) {
            u64t w2 = *(const u64t*)(wrow + kk);
#pragma unroll
            for (int i = 0; i < HEAD_ITEMS; i++) {
                u64t h2 = *(const u64t*)&Hs[i][kk];
                FFMA2(acc2[i], h2, w2);
            }
        }
        __syncthreads();
    }

    float bias = infB[c * NOO + o];
#pragma unroll
    for (int i = 0; i < HEAD_ITEMS; i++) {
        int it = sIt[i];
        if (it >= 0) {
            float lo, hi;
            UNPACK2(lo, hi, acc2[i]);
            int tt = it >> 16, bb = it & 0xFFFF;
            out[((size_t)tt * BB + bb) * NOO + o] = lo + hi + bias;
        }
    }
}

// ---------------- launcher ----------------
extern "C" void kernel_launch(void* const* d_in, const int* in_sizes, int n_in,
                              void* d_out, int out_size) {
    const int* program      = (const int*)d_in[0];
    const int* plen         = (const int*)d_in[1];
    const int* trace        = (const int*)d_in[2];
    const int* choices      = (const int*)d_in[3];
    const float* enc_embed  = (const float*)d_in[4];
    const float* lstm_W_ih  = (const float*)d_in[5];
    const float* lstm_W_hh  = (const float*)d_in[6];
    const float* lstm_b_ih  = (const float*)d_in[7];
    const float* lstm_b_hh  = (const float*)d_in[8];
    const float* h0         = (const float*)d_in[9];
    const float* c0         = (const float*)d_in[10];
    const float* index_embed= (const float*)d_in[11];
    const float* choice_tab = (const float*)d_in[12];
    const float* gru_W_ih   = (const float*)d_in[13];
    const float* gru_W_hh   = (const float*)d_in[14];
    const float* gru_b_ih   = (const float*)d_in[15];
    const float* gru_b_hh   = (const float*)d_in[16];
    const float* bn_gamma   = (const float*)d_in[17];
    const float* bn_beta    = (const float*)d_in[18];
    const float* inf_W      = (const float*)d_in[19];
    const float* inf_b      = (const float*)d_in[20];
    const float* h_dec0     = (const float*)d_in[21];
    float* out = (float*)d_out;

    const int LSTM_SMEM = (4 * WGSZ + 32 * ASTRIDE) * 4;              // 165376 B
    const int GRU_SMEM  = (3 * WGSZ + 32 * ASTRIDE + 2 * HH) * 4;     // 134400 B
    cudaFuncSetAttribute(lstm_persist, cudaFuncAttributeMaxDynamicSharedMemorySize, LSTM_SMEM);
    cudaFuncSetAttribute(gru_persist, cudaFuncAttributeMaxDynamicSharedMemorySize, GRU_SMEM);

    init_kernel<<<4096, 256>>>(out, out_size);
    stats0_kernel<<<16, 256>>>(h_dec0);

    // token -> LSTM gate_x table: [10000,1024] = embed @ Wih^T + b_ih + b_hh
    gemm_nt<<<dim3(16, 157), 256>>>(enc_embed, EE, lstm_W_ih, EE,
                                    lstm_b_ih, lstm_b_hh, VV, 4 * HH, EE, 0, 0);
    // (prev,val) -> GRU gx part: [16384,768] = choice_tables @ Wih[:, 0:300]^T
    gemm_nt<<<dim3(12, 256), 256>>>(choice_tab, EE, gru_W_ih, HH + 2 * EE,
                                    nullptr, nullptr, NCC * NOO, 3 * HH, EE, 1, 0);
    // prev -> GRU gx part: [64,768] = index_embed @ Wih[:, 556:856]^T
    gemm_nt<<<dim3(12, 1), 256>>>(index_embed, EE, gru_W_ih + (HH + EE), HH + 2 * EE,
                                  nullptr, nullptr, NCC, 3 * HH, EE, 2, 0);

    // head binning (independent of recurrences)
    count_kernel<<<(NITEMS + 255) / 256, 256>>>(trace);
    prefix_kernel<<<1, 32>>>();
    scatter_kernel<<<(NITEMS + 255) / 256, 256>>>(trace);

    // persistent encoder recurrence (final h lands in g_hB)
    lstm_persist<<<NBLK, 256, LSTM_SMEM>>>(lstm_W_hh, program, plen, h0, c0);

    // prog_emb -> GRU gx part + b_ih: [512,768] (A = g_hB via selector)
    gemm_nt<<<dim3(12, 8), 256>>>(nullptr, HH, gru_W_ih + EE, HH + 2 * EE,
                                  gru_b_ih, nullptr, BB, 3 * HH, HH, 3, 1);

    // persistent decoder recurrence
    gru_persist<<<NBLK, 256, GRU_SMEM>>>(gru_W_hh, gru_b_hh, bn_gamma, bn_beta,
                                         trace, choices, h_dec0);

    // routed output head
    head_kernel<<<ITEM_CAP / HEAD_ITEMS, 256>>>(trace, inf_W, inf_b, out);
}